// round 11
// baseline (speedup 1.0000x reference)
#include <cuda_runtime.h>
#include <math.h>

// ---------------------------------------------------------------------------
// SimpleRetention (real-output build, 8x4 register tiles).
// Re(out[b,n,h]) = sum_m gamma^(n-m)[n>=m] * Re(Q K^T)[b,n,m] * V[b,m,h]
// Re(QK^T)[n,m] = dot(QQ[n], KK[m]) over K=512 with QQ=[Qc|Qs], KK=[Kc|Ks].
// Decay window 128: gamma^128 ~ 1.4e-6 relative truncation (threshold 1e-3).
// ---------------------------------------------------------------------------

namespace {
constexpr int BATCH = 4;
constexpr int SEQ   = 2048;
constexpr int HD    = 256;
constexpr int K2W   = 2 * HD;             // 512
constexpr int WIN   = 128;
constexpr int NROW  = BATCH * SEQ;        // 8192
constexpr int NJ    = WIN / 64 + 1;       // 3
constexpr float LOG2_GAMMA = -0.15200309344504997f;  // log2(0.9)
}

// scratch
__device__ float2 g_rot [SEQ * HD];
__device__ float  g_QQ  [NROW * K2W];
__device__ float  g_KK  [NROW * K2W];
__device__ float  g_Vm  [NROW * HD];
__device__ float  g_attR[NROW * WIN];

// ---------------------------------------------------------------------------
// K0: rotation table
// ---------------------------------------------------------------------------
__global__ __launch_bounds__(256) void rot_kernel(const float* __restrict__ theta)
{
    int idx = blockIdx.x * 256 + threadIdx.x;
    int s = idx >> 8;
    int h = idx & (HD - 1);
    float ph = (float)(s + 1) * theta[h];
    float sn, cs;
    sincosf(ph, &sn, &cs);
    g_rot[idx] = make_float2(cs, sn);
}

// ---------------------------------------------------------------------------
// K1: projections + rotation epilogue. 128x64 tile, 256 threads, 8x4/thread.
// z: 0->Q, 1->K, 2->V.  grid (NROW/128, HD/64, 3)
// ---------------------------------------------------------------------------
__global__ __launch_bounds__(256) void proj_kernel(
    const float* __restrict__ X,  const float* __restrict__ Wq,
    const float* __restrict__ Wk, const float* __restrict__ Wv)
{
    __shared__ __align__(16) float As[32][132];   // X tile, [k][row], 128 rows
    __shared__ __align__(16) float Bs[32][68];    // W tile, [k][col], 64 cols

    const int z    = blockIdx.z;
    const float* Wm = (z == 0) ? Wq : (z == 1) ? Wk : Wv;
    const int row0 = blockIdx.x * 128;
    const int col0 = blockIdx.y * 64;
    const int tid  = threadIdx.x;
    const int tx   = tid & 15, ty = tid >> 4;     // ty 0..15
    const int r0   = ty * 8,  c0 = tx * 4;

    float acc[8][4] = {};

    for (int kk = 0; kk < HD; kk += 32) {
        for (int i = tid; i < 128 * 32; i += 256) {
            int r = i >> 5, k = i & 31;
            As[k][r] = X[(row0 + r) * HD + kk + k];
        }
        for (int i = tid; i < 32 * 64; i += 256) {
            int k = i >> 6, c = i & 63;
            Bs[k][c] = Wm[(kk + k) * HD + col0 + c];
        }
        __syncthreads();

        #pragma unroll 8
        for (int k = 0; k < 32; k++) {
            float4 a0 = *(const float4*)&As[k][r0];
            float4 a1 = *(const float4*)&As[k][r0 + 4];
            float4 b  = *(const float4*)&Bs[k][c0];
            const float av[8] = {a0.x, a0.y, a0.z, a0.w, a1.x, a1.y, a1.z, a1.w};
            const float bv[4] = {b.x, b.y, b.z, b.w};
            #pragma unroll
            for (int i = 0; i < 8; i++)
                #pragma unroll
                for (int j = 0; j < 4; j++)
                    acc[i][j] += av[i] * bv[j];
        }
        __syncthreads();
    }

    if (z == 2) {
        #pragma unroll
        for (int i = 0; i < 8; i++)
            #pragma unroll
            for (int j = 0; j < 4; j++)
                g_Vm[(row0 + r0 + i) * HD + col0 + c0 + j] = acc[i][j];
    } else {
        float* dst = (z == 0) ? g_QQ : g_KK;
        #pragma unroll
        for (int i = 0; i < 8; i++) {
            int row = row0 + r0 + i;
            int s   = row & (SEQ - 1);
            #pragma unroll
            for (int j = 0; j < 4; j++) {
                int h = col0 + c0 + j;
                float2 rt = g_rot[s * HD + h];
                dst[row * K2W + h]      = acc[i][j] * rt.x;
                dst[row * K2W + HD + h] = acc[i][j] * rt.y;
            }
        }
    }
}

// ---------------------------------------------------------------------------
// K2: real banded attention = QQ . KK^T (K=512), decayed.
// 64x64 tile, 128 threads, 8x4/thread.  grid (SEQ/64, NJ, BATCH)
// ---------------------------------------------------------------------------
__global__ __launch_bounds__(128) void att_kernel()
{
    __shared__ __align__(16) float As[32][68];
    __shared__ __align__(16) float Bs[32][68];

    const int b  = blockIdx.z;
    const int n0 = blockIdx.x * 64;
    const int m0 = n0 - 64 * (int)blockIdx.y;
    if (m0 < 0) return;

    const int tid = threadIdx.x;
    const int tx  = tid & 15, ty = tid >> 4;      // ty 0..7
    const int r0  = ty * 8,  c0 = tx * 4;
    const int qbase = (b * SEQ + n0) * K2W;
    const int kbase = (b * SEQ + m0) * K2W;

    float acc[8][4] = {};

    for (int kk = 0; kk < K2W; kk += 32) {
        for (int i = tid; i < 64 * 32; i += 128) {
            int r = i >> 5, k = i & 31;
            As[k][r] = g_QQ[qbase + r * K2W + kk + k];
            Bs[k][r] = g_KK[kbase + r * K2W + kk + k];
        }
        __syncthreads();

        #pragma unroll 8
        for (int k = 0; k < 32; k++) {
            float4 a0 = *(const float4*)&As[k][r0];
            float4 a1 = *(const float4*)&As[k][r0 + 4];
            float4 bb = *(const float4*)&Bs[k][c0];
            const float av[8] = {a0.x, a0.y, a0.z, a0.w, a1.x, a1.y, a1.z, a1.w};
            const float bv[4] = {bb.x, bb.y, bb.z, bb.w};
            #pragma unroll
            for (int i = 0; i < 8; i++)
                #pragma unroll
                for (int j = 0; j < 4; j++)
                    acc[i][j] += av[i] * bv[j];
        }
        __syncthreads();
    }

    #pragma unroll
    for (int i = 0; i < 8; i++) {
        int n = n0 + r0 + i;
        #pragma unroll
        for (int j = 0; j < 4; j++) {
            int m = m0 + c0 + j;
            int d = n - m;
            if (d >= 0 && d < WIN) {
                float dec = exp2f((float)d * LOG2_GAMMA);
                g_attR[(b * SEQ + n) * WIN + d] = acc[i][j] * dec;
            }
        }
    }
}

// ---------------------------------------------------------------------------
// K3: Re(out)[b,n,h] = sum_m attR[b,n,n-m] * V[b,m,h]
// 64x64 tile, 128 threads, 8x4/thread.  Band tile stored [m][n] so the inner
// loop reads A as vectorized LDS.128.  grid (SEQ/64, HD/64, BATCH)
// ---------------------------------------------------------------------------
__global__ __launch_bounds__(128) void out_kernel(float* __restrict__ out,
                                                  long long out_elems)
{
    __shared__ __align__(16) float Am[64][68];    // band, [m][n]
    __shared__ __align__(16) float Vs[64][68];    // V,    [m][h]

    const int b  = blockIdx.z;
    const int n0 = blockIdx.x * 64;
    const int h0 = blockIdx.y * 64;
    const int tid = threadIdx.x;
    const int tx  = tid & 15, ty = tid >> 4;      // ty 0..7
    const int r0  = ty * 8,  c0 = tx * 4;

    float acc[8][4] = {};

    for (int jt = 0; jt < NJ; jt++) {
        int m0 = n0 - 64 * jt;
        if (m0 < 0) break;

        for (int i = tid; i < 64 * 64; i += 128) {
            int r = i >> 6, c = i & 63;
            Vs[r][c] = g_Vm[(b * SEQ + m0 + r) * HD + h0 + c];
        }
        // Am[ml][nl]; gmem read coalesced over ml (d descends contiguously)
        for (int i = tid; i < 64 * 64; i += 128) {
            int ml = i & 63, nl = i >> 6;
            int d = 64 * jt + nl - ml;
            Am[ml][nl] = (d >= 0 && d < WIN)
                       ? g_attR[(b * SEQ + n0 + nl) * WIN + d]
                       : 0.0f;
        }
        __syncthreads();

        #pragma unroll 8
        for (int m = 0; m < 64; m++) {
            float4 a0 = *(const float4*)&Am[m][r0];
            float4 a1 = *(const float4*)&Am[m][r0 + 4];
            float4 v  = *(const float4*)&Vs[m][c0];
            const float av[8] = {a0.x, a0.y, a0.z, a0.w, a1.x, a1.y, a1.z, a1.w};
            const float vv[4] = {v.x, v.y, v.z, v.w};
            #pragma unroll
            for (int i = 0; i < 8; i++)
                #pragma unroll
                for (int j = 0; j < 4; j++)
                    acc[i][j] += av[i] * vv[j];
        }
        __syncthreads();
    }

    #pragma unroll
    for (int i = 0; i < 8; i++) {
        int n = n0 + r0 + i;
        #pragma unroll
        for (int j = 0; j < 4; j++) {
            int h = h0 + c0 + j;
            long long idx = ((long long)b * SEQ + n) * HD + h;
            if (idx < out_elems)
                out[idx] = acc[i][j];
        }
    }
}

// ---------------------------------------------------------------------------
// launch
// ---------------------------------------------------------------------------
extern "C" void kernel_launch(void* const* d_in, const int* in_sizes, int n_in,
                              void* d_out, int out_size)
{
    constexpr int XN = BATCH * SEQ * HD;
    constexpr int WN = HD * HD;
    constexpr int TN = HD;

    const float* X = nullptr;
    const float* theta = nullptr;
    const float* W[3] = {nullptr, nullptr, nullptr};
    int wn = 0;

    for (int i = 0; i < n_in; i++) {
        int s = in_sizes[i];
        if (s == XN)                X = (const float*)d_in[i];
        else if (s == TN)           theta = (const float*)d_in[i];
        else if (s == WN && wn < 3) W[wn++] = (const float*)d_in[i];
    }
    if (!X || !theta || wn < 3) return;

    float* out = (float*)d_out;

    rot_kernel<<<SEQ * HD / 256, 256>>>(theta);
    proj_kernel<<<dim3(NROW / 128, HD / 64, 3), 256>>>(X, W[0], W[1], W[2]);
    att_kernel<<<dim3(SEQ / 64, NJ, BATCH), 128>>>();
    out_kernel<<<dim3(SEQ / 64, HD / 64, BATCH), 128>>>(out, (long long)out_size);
}

// round 13
// speedup vs baseline: 1.3146x; 1.3146x over previous
#include <cuda_runtime.h>
#include <cuda_bf16.h>
#include <math.h>

// ---------------------------------------------------------------------------
// SimpleRetention (real-output build).
// Re(out[b,n,h]) = sum_m gamma^(n-m)[n>=m] * Re(Q K^T)[b,n,m] * V[b,m,h]
// Re(QK^T)[n,m] = dot(QQ[n], KK[m]) over K=512 with QQ=[Qc|Qs], KK=[Kc|Ks].
// Decay window 128: gamma^128 ~ 1.4e-6 relative truncation (threshold 1e-3).
// proj: mma.sync bf16 (baseline PTX, works on sm_103 target) with hi/lo
//       error-compensated split -> rel err ~1.5e-5.
// att/out: best scalar config (R9: 4x4 tiles, 256 threads).
// ---------------------------------------------------------------------------

namespace {
constexpr int BATCH = 4;
constexpr int SEQ   = 2048;
constexpr int HD    = 256;
constexpr int K2W   = 2 * HD;             // 512
constexpr int WIN   = 128;
constexpr int NROW  = BATCH * SEQ;        // 8192
constexpr int NJ    = WIN / 64 + 1;       // 3
constexpr float LOG2_GAMMA = -0.15200309344504997f;

// proj mma tiling
constexpr int PM = 128;                   // block M
constexpr int PN = 64;                    // block N
constexpr int KC = 32;                    // K chunk (bf16)
constexpr int SSTR = KC + 8;              // smem row stride (bf16 elems) = 40
}

// scratch
__device__ float2        g_rot [SEQ * HD];
__device__ float         g_QQ  [NROW * K2W];
__device__ float         g_KK  [NROW * K2W];
__device__ float         g_Vm  [NROW * HD];
__device__ float         g_attR[NROW * WIN];
__device__ __nv_bfloat16 g_Wh  [3 * HD * HD];   // W^T split-hi  [w][n][k]
__device__ __nv_bfloat16 g_Wl  [3 * HD * HD];   // W^T split-lo

// ---------------------------------------------------------------------------
// K0: rotation table
// ---------------------------------------------------------------------------
__global__ __launch_bounds__(256) void rot_kernel(const float* __restrict__ theta)
{
    int idx = blockIdx.x * 256 + threadIdx.x;
    int s = idx >> 8;
    int h = idx & (HD - 1);
    float ph = (float)(s + 1) * theta[h];
    float sn, cs;
    sincosf(ph, &sn, &cs);
    g_rot[idx] = make_float2(cs, sn);
}

// ---------------------------------------------------------------------------
// K0b: transpose + bf16-split weights:  g_W{h,l}[w][n][k] = W[w][k][n]
// ---------------------------------------------------------------------------
__global__ __launch_bounds__(256) void wconv_kernel(
    const float* __restrict__ W0, const float* __restrict__ W1,
    const float* __restrict__ W2)
{
    int o = blockIdx.x * 256 + threadIdx.x;            // 3*65536
    int w = o >> 16;
    int n = (o >> 8) & 255;
    int k = o & 255;
    const float* W = (w == 0) ? W0 : (w == 1) ? W1 : W2;
    float x = W[k * HD + n];
    __nv_bfloat16 hi = __float2bfloat16(x);
    __nv_bfloat16 lo = __float2bfloat16(x - __bfloat162float(hi));
    g_Wh[o] = hi;
    g_Wl[o] = lo;
}

// ---------------------------------------------------------------------------
// mma.sync m16n8k16 bf16 (row.col), fp32 accumulate
// ---------------------------------------------------------------------------
__device__ __forceinline__ void mma_bf16(
    float& d0, float& d1, float& d2, float& d3,
    unsigned a0, unsigned a1, unsigned a2, unsigned a3,
    unsigned b0, unsigned b1)
{
    asm volatile(
        "mma.sync.aligned.m16n8k16.row.col.f32.bf16.bf16.f32 "
        "{%0,%1,%2,%3}, {%4,%5,%6,%7}, {%8,%9}, {%0,%1,%2,%3};"
        : "+f"(d0), "+f"(d1), "+f"(d2), "+f"(d3)
        : "r"(a0), "r"(a1), "r"(a2), "r"(a3), "r"(b0), "r"(b1));
}

// ---------------------------------------------------------------------------
// K1: proj via mma.sync.  grid (NROW/128, HD/64, 3), 256 threads (8 warps).
// Each warp computes a 32x32 output tile (2 m-frags x 4 n-frags).
// z: 0->Q, 1->K, 2->V.
// ---------------------------------------------------------------------------
__global__ __launch_bounds__(256) void proj_kernel(const float* __restrict__ X)
{
    __shared__ __align__(16) __nv_bfloat16 Ah[PM * SSTR];
    __shared__ __align__(16) __nv_bfloat16 Al[PM * SSTR];
    __shared__ __align__(16) __nv_bfloat16 Bh[PN * SSTR];
    __shared__ __align__(16) __nv_bfloat16 Bl[PN * SSTR];

    const int tid  = threadIdx.x;
    const int wid  = tid >> 5;
    const int lane = tid & 31;
    const int row0 = blockIdx.x * PM;
    const int col0 = blockIdx.y * PN;
    const int z    = blockIdx.z;

    const int warp_m = wid & 3;          // 0..3
    const int warp_n = wid >> 2;         // 0..1
    const int wr0 = warp_m * 32;         // warp row base (local)
    const int wc0 = warp_n * 32;         // warp col base (local)

    const __nv_bfloat16* Wh = g_Wh + z * HD * HD;
    const __nv_bfloat16* Wl = g_Wl + z * HD * HD;

    float acc[2][4][4] = {};             // [mi][nj][4]

    const int lr = lane >> 2;            // lane row group 0..7
    const int lk = (lane & 3) * 2;       // lane k base

    for (int k0 = 0; k0 < HD; k0 += KC) {
        // A: X[row0..+127][k0..+31] -> bf16 hi/lo
        for (int i = tid; i < PM * (KC / 2); i += 256) {
            int r = i >> 4, kp = i & 15;
            float2 x2 = *(const float2*)&X[(row0 + r) * HD + k0 + kp * 2];
            __nv_bfloat16 h0 = __float2bfloat16(x2.x);
            __nv_bfloat16 h1 = __float2bfloat16(x2.y);
            __nv_bfloat16 l0 = __float2bfloat16(x2.x - __bfloat162float(h0));
            __nv_bfloat16 l1 = __float2bfloat16(x2.y - __bfloat162float(h1));
            *(__nv_bfloat162*)&Ah[r * SSTR + kp * 2] = __nv_bfloat162(h0, h1);
            *(__nv_bfloat162*)&Al[r * SSTR + kp * 2] = __nv_bfloat162(l0, l1);
        }
        // B: pre-split W^T[col0..+63][k0..+31]
        for (int i = tid; i < PN * (KC / 2); i += 256) {
            int n = i >> 4, kp = i & 15;
            unsigned gi = (unsigned)(col0 + n) * HD + k0 + kp * 2;
            *(unsigned*)&Bh[n * SSTR + kp * 2] = *(const unsigned*)&Wh[gi];
            *(unsigned*)&Bl[n * SSTR + kp * 2] = *(const unsigned*)&Wl[gi];
        }
        __syncthreads();

        #pragma unroll
        for (int ks = 0; ks < KC; ks += 16) {
            // A fragments (hi & lo) for 2 m-subtiles
            unsigned ah[2][4], al[2][4];
            #pragma unroll
            for (int mi = 0; mi < 2; mi++) {
                int r = wr0 + mi * 16 + lr;
                ah[mi][0] = *(const unsigned*)&Ah[r * SSTR + ks + lk];
                ah[mi][1] = *(const unsigned*)&Ah[(r + 8) * SSTR + ks + lk];
                ah[mi][2] = *(const unsigned*)&Ah[r * SSTR + ks + 8 + lk];
                ah[mi][3] = *(const unsigned*)&Ah[(r + 8) * SSTR + ks + 8 + lk];
                al[mi][0] = *(const unsigned*)&Al[r * SSTR + ks + lk];
                al[mi][1] = *(const unsigned*)&Al[(r + 8) * SSTR + ks + lk];
                al[mi][2] = *(const unsigned*)&Al[r * SSTR + ks + 8 + lk];
                al[mi][3] = *(const unsigned*)&Al[(r + 8) * SSTR + ks + 8 + lk];
            }
            // B fragments (hi & lo) for 4 n-subtiles
            unsigned bh[4][2], bl[4][2];
            #pragma unroll
            for (int nj = 0; nj < 4; nj++) {
                int n = wc0 + nj * 8 + lr;
                bh[nj][0] = *(const unsigned*)&Bh[n * SSTR + ks + lk];
                bh[nj][1] = *(const unsigned*)&Bh[n * SSTR + ks + 8 + lk];
                bl[nj][0] = *(const unsigned*)&Bl[n * SSTR + ks + lk];
                bl[nj][1] = *(const unsigned*)&Bl[n * SSTR + ks + 8 + lk];
            }
            #pragma unroll
            for (int mi = 0; mi < 2; mi++)
                #pragma unroll
                for (int nj = 0; nj < 4; nj++) {
                    float* d = acc[mi][nj];
                    mma_bf16(d[0], d[1], d[2], d[3],
                             ah[mi][0], ah[mi][1], ah[mi][2], ah[mi][3],
                             bh[nj][0], bh[nj][1]);
                    mma_bf16(d[0], d[1], d[2], d[3],
                             ah[mi][0], ah[mi][1], ah[mi][2], ah[mi][3],
                             bl[nj][0], bl[nj][1]);
                    mma_bf16(d[0], d[1], d[2], d[3],
                             al[mi][0], al[mi][1], al[mi][2], al[mi][3],
                             bh[nj][0], bh[nj][1]);
                }
        }
        __syncthreads();
    }

    // epilogue: fragment layout c0,c1 -> (row, col..col+1); c2,c3 -> (row+8, ..)
    #pragma unroll
    for (int mi = 0; mi < 2; mi++) {
        #pragma unroll
        for (int nj = 0; nj < 4; nj++) {
            int rloc = wr0 + mi * 16 + lr;
            int hloc = wc0 + nj * 8 + (lane & 3) * 2;
            #pragma unroll
            for (int half = 0; half < 2; half++) {
                int row = row0 + rloc + half * 8;
                float d0 = acc[mi][nj][half * 2];
                float d1 = acc[mi][nj][half * 2 + 1];
                int h = col0 + hloc;
                if (z == 2) {
                    g_Vm[row * HD + h]     = d0;
                    g_Vm[row * HD + h + 1] = d1;
                } else {
                    float* dst = (z == 0) ? g_QQ : g_KK;
                    int s = row & (SEQ - 1);
                    float2 rt0 = g_rot[s * HD + h];
                    float2 rt1 = g_rot[s * HD + h + 1];
                    dst[row * K2W + h]          = d0 * rt0.x;
                    dst[row * K2W + h + 1]      = d1 * rt1.x;
                    dst[row * K2W + HD + h]     = d0 * rt0.y;
                    dst[row * K2W + HD + h + 1] = d1 * rt1.y;
                }
            }
        }
    }
}

// ---------------------------------------------------------------------------
// K2: real banded attention = QQ . KK^T (K=512), decayed.  (R9 scalar config)
// ---------------------------------------------------------------------------
__global__ __launch_bounds__(256) void att_kernel()
{
    __shared__ __align__(16) float As[32][68];
    __shared__ __align__(16) float Bs[32][68];

    const int b  = blockIdx.z;
    const int n0 = blockIdx.x * 64;
    const int m0 = n0 - 64 * (int)blockIdx.y;
    if (m0 < 0) return;

    const int tid = threadIdx.x;
    const int tx  = tid & 15, ty = tid >> 4;
    const int r0  = ty * 4,  c0 = tx * 4;
    const int qbase = (b * SEQ + n0) * K2W;
    const int kbase = (b * SEQ + m0) * K2W;

    float acc[4][4] = {};

    for (int kk = 0; kk < K2W; kk += 32) {
        for (int i = tid; i < 64 * 32; i += 256) {
            int r = i >> 5, k = i & 31;
            As[k][r] = g_QQ[qbase + r * K2W + kk + k];
            Bs[k][r] = g_KK[kbase + r * K2W + kk + k];
        }
        __syncthreads();

        #pragma unroll 8
        for (int k = 0; k < 32; k++) {
            float4 a = *(const float4*)&As[k][r0];
            float4 bb = *(const float4*)&Bs[k][c0];
            const float av[4] = {a.x, a.y, a.z, a.w};
            const float bv[4] = {bb.x, bb.y, bb.z, bb.w};
            #pragma unroll
            for (int i = 0; i < 4; i++)
                #pragma unroll
                for (int j = 0; j < 4; j++)
                    acc[i][j] += av[i] * bv[j];
        }
        __syncthreads();
    }

    #pragma unroll
    for (int i = 0; i < 4; i++) {
        int n = n0 + r0 + i;
        #pragma unroll
        for (int j = 0; j < 4; j++) {
            int m = m0 + c0 + j;
            int d = n - m;
            if (d >= 0 && d < WIN) {
                float dec = exp2f((float)d * LOG2_GAMMA);
                g_attR[(b * SEQ + n) * WIN + d] = acc[i][j] * dec;
            }
        }
    }
}

// ---------------------------------------------------------------------------
// K3: Re(out)[b,n,h] = sum_m attR[b,n,n-m] * V[b,m,h]   (R9 scalar config)
// ---------------------------------------------------------------------------
__global__ __launch_bounds__(256) void out_kernel(float* __restrict__ out,
                                                  long long out_elems)
{
    __shared__ __align__(16) float Ar[64][68];
    __shared__ __align__(16) float Vs[64][68];

    const int b  = blockIdx.z;
    const int n0 = blockIdx.x * 64;
    const int h0 = blockIdx.y * 64;
    const int tid = threadIdx.x;
    const int tx  = tid & 15, ty = tid >> 4;
    const int r0  = ty * 4,  c0 = tx * 4;

    float acc[4][4] = {};

    for (int jt = 0; jt < NJ; jt++) {
        int m0 = n0 - 64 * jt;
        if (m0 < 0) break;

        for (int i = tid; i < 64 * 64; i += 256) {
            int r = i >> 6, c = i & 63;
            Vs[r][c] = g_Vm[(b * SEQ + m0 + r) * HD + h0 + c];
        }
        for (int i = tid; i < 64 * 64; i += 256) {
            int nl = i >> 6, ml = i & 63;
            int d = 64 * jt + nl - ml;
            Ar[nl][ml] = (d >= 0 && d < WIN)
                       ? g_attR[(b * SEQ + n0 + nl) * WIN + d]
                       : 0.0f;
        }
        __syncthreads();

        #pragma unroll 8
        for (int m = 0; m < 64; m++) {
            float4 v = *(const float4*)&Vs[m][c0];
            const float vv[4] = {v.x, v.y, v.z, v.w};
            float ar[4];
            #pragma unroll
            for (int i = 0; i < 4; i++) ar[i] = Ar[r0 + i][m];
            #pragma unroll
            for (int i = 0; i < 4; i++)
                #pragma unroll
                for (int j = 0; j < 4; j++)
                    acc[i][j] += ar[i] * vv[j];
        }
        __syncthreads();
    }

    #pragma unroll
    for (int i = 0; i < 4; i++) {
        int n = n0 + r0 + i;
        #pragma unroll
        for (int j = 0; j < 4; j++) {
            int h = h0 + c0 + j;
            long long idx = ((long long)b * SEQ + n) * HD + h;
            if (idx < out_elems)
                out[idx] = acc[i][j];
        }
    }
}

// ---------------------------------------------------------------------------
// launch
// ---------------------------------------------------------------------------
extern "C" void kernel_launch(void* const* d_in, const int* in_sizes, int n_in,
                              void* d_out, int out_size)
{
    constexpr int XN = BATCH * SEQ * HD;
    constexpr int WN = HD * HD;
    constexpr int TN = HD;

    const float* X = nullptr;
    const float* theta = nullptr;
    const float* W[3] = {nullptr, nullptr, nullptr};
    int wn = 0;

    for (int i = 0; i < n_in; i++) {
        int s = in_sizes[i];
        if (s == XN)                X = (const float*)d_in[i];
        else if (s == TN)           theta = (const float*)d_in[i];
        else if (s == WN && wn < 3) W[wn++] = (const float*)d_in[i];
    }
    if (!X || !theta || wn < 3) return;

    float* out = (float*)d_out;

    rot_kernel<<<SEQ * HD / 256, 256>>>(theta);
    wconv_kernel<<<3 * HD * HD / 256, 256>>>(W[0], W[1], W[2]);
    proj_kernel<<<dim3(NROW / PM, HD / PN, 3), 256>>>(X);
    att_kernel<<<dim3(SEQ / 64, NJ, BATCH), 256>>>();
    out_kernel<<<dim3(SEQ / 64, HD / 64, BATCH), 256>>>(out, (long long)out_size);
}

// round 14
// speedup vs baseline: 1.5707x; 1.1948x over previous
#include <cuda_runtime.h>
#include <cuda_bf16.h>
#include <math.h>

// ---------------------------------------------------------------------------
// SimpleRetention (real-output build).
// Re(out[b,n,h]) = sum_m gamma^(n-m)[n>=m] * Re(Q K^T)[b,n,m] * V[b,m,h]
// Re(QK^T)[n,m] = dot(QQ[n], KK[m]) over K=512 with QQ=[Qc|Qs], KK=[Kc|Ks].
// Decay window 128: gamma^128 ~ 1.4e-6 relative truncation (threshold 1e-3).
// proj AND att run on mma.sync bf16 with hi/lo error-compensated split
// (hi*hi + hi*lo + lo*hi, fp32 accum). QQ/KK live in gmem as split bf16.
// out stays scalar (R9 config) - next candidate.
// ---------------------------------------------------------------------------

namespace {
constexpr int BATCH = 4;
constexpr int SEQ   = 2048;
constexpr int HD    = 256;
constexpr int K2W   = 2 * HD;             // 512
constexpr int WIN   = 128;
constexpr int NROW  = BATCH * SEQ;        // 8192
constexpr int NJ    = WIN / 64 + 1;       // 3
constexpr float LOG2_GAMMA = -0.15200309344504997f;

constexpr int PM = 128;                   // proj block M
constexpr int PN = 64;                    // proj block N
constexpr int KC = 32;                    // K chunk (bf16)
constexpr int SSTR = KC + 8;              // smem row stride (bf16) = 40
}

// scratch
__device__ float2        g_rot [SEQ * HD];
__device__ __nv_bfloat16 g_QQh [NROW * K2W];   // rotated Q, split hi
__device__ __nv_bfloat16 g_QQl [NROW * K2W];   // rotated Q, split lo
__device__ __nv_bfloat16 g_KKh [NROW * K2W];
__device__ __nv_bfloat16 g_KKl [NROW * K2W];
__device__ float         g_Vm  [NROW * HD];
__device__ float         g_attR[NROW * WIN];
__device__ __nv_bfloat16 g_Wh  [3 * HD * HD];  // W^T split-hi [w][n][k]
__device__ __nv_bfloat16 g_Wl  [3 * HD * HD];

__device__ __forceinline__ __nv_bfloat162 split_hi2(float a, float b,
                                                    __nv_bfloat162& lo)
{
    __nv_bfloat16 h0 = __float2bfloat16(a);
    __nv_bfloat16 h1 = __float2bfloat16(b);
    lo = __nv_bfloat162(__float2bfloat16(a - __bfloat162float(h0)),
                        __float2bfloat16(b - __bfloat162float(h1)));
    return __nv_bfloat162(h0, h1);
}

// ---------------------------------------------------------------------------
// K0: rotation table
// ---------------------------------------------------------------------------
__global__ __launch_bounds__(256) void rot_kernel(const float* __restrict__ theta)
{
    int idx = blockIdx.x * 256 + threadIdx.x;
    int s = idx >> 8;
    int h = idx & (HD - 1);
    float ph = (float)(s + 1) * theta[h];
    float sn, cs;
    sincosf(ph, &sn, &cs);
    g_rot[idx] = make_float2(cs, sn);
}

// ---------------------------------------------------------------------------
// K0b: transpose + bf16-split weights:  g_W{h,l}[w][n][k] = W[w][k][n]
// ---------------------------------------------------------------------------
__global__ __launch_bounds__(256) void wconv_kernel(
    const float* __restrict__ W0, const float* __restrict__ W1,
    const float* __restrict__ W2)
{
    int o = blockIdx.x * 256 + threadIdx.x;
    int w = o >> 16;
    int n = (o >> 8) & 255;
    int k = o & 255;
    const float* W = (w == 0) ? W0 : (w == 1) ? W1 : W2;
    float x = W[k * HD + n];
    __nv_bfloat16 hi = __float2bfloat16(x);
    g_Wh[o] = hi;
    g_Wl[o] = __float2bfloat16(x - __bfloat162float(hi));
}

// ---------------------------------------------------------------------------
// mma.sync m16n8k16 bf16 (row.col), fp32 accumulate
// ---------------------------------------------------------------------------
__device__ __forceinline__ void mma_bf16(
    float& d0, float& d1, float& d2, float& d3,
    unsigned a0, unsigned a1, unsigned a2, unsigned a3,
    unsigned b0, unsigned b1)
{
    asm volatile(
        "mma.sync.aligned.m16n8k16.row.col.f32.bf16.bf16.f32 "
        "{%0,%1,%2,%3}, {%4,%5,%6,%7}, {%8,%9}, {%0,%1,%2,%3};"
        : "+f"(d0), "+f"(d1), "+f"(d2), "+f"(d3)
        : "r"(a0), "r"(a1), "r"(a2), "r"(a3), "r"(b0), "r"(b1));
}

// ---------------------------------------------------------------------------
// K1: proj via mma.sync.  grid (NROW/128, HD/64, 3), 256 threads (8 warps).
// z: 0->Q, 1->K, 2->V. Epilogue: rotate, split to bf16 hi/lo (Q/K) or fp32 (V).
// ---------------------------------------------------------------------------
__global__ __launch_bounds__(256) void proj_kernel(const float* __restrict__ X)
{
    __shared__ __align__(16) __nv_bfloat16 Ah[PM * SSTR];
    __shared__ __align__(16) __nv_bfloat16 Al[PM * SSTR];
    __shared__ __align__(16) __nv_bfloat16 Bh[PN * SSTR];
    __shared__ __align__(16) __nv_bfloat16 Bl[PN * SSTR];

    const int tid  = threadIdx.x;
    const int wid  = tid >> 5;
    const int lane = tid & 31;
    const int row0 = blockIdx.x * PM;
    const int col0 = blockIdx.y * PN;
    const int z    = blockIdx.z;

    const int wr0 = (wid & 3) * 32;
    const int wc0 = (wid >> 2) * 32;
    const int lr  = lane >> 2;
    const int lk  = (lane & 3) * 2;

    const __nv_bfloat16* Wh = g_Wh + z * HD * HD;
    const __nv_bfloat16* Wl = g_Wl + z * HD * HD;

    float acc[2][4][4] = {};

    for (int k0 = 0; k0 < HD; k0 += KC) {
        for (int i = tid; i < PM * (KC / 2); i += 256) {
            int r = i >> 4, kp = i & 15;
            float2 x2 = *(const float2*)&X[(row0 + r) * HD + k0 + kp * 2];
            __nv_bfloat162 lo2;
            __nv_bfloat162 hi2 = split_hi2(x2.x, x2.y, lo2);
            *(__nv_bfloat162*)&Ah[r * SSTR + kp * 2] = hi2;
            *(__nv_bfloat162*)&Al[r * SSTR + kp * 2] = lo2;
        }
        for (int i = tid; i < PN * (KC / 2); i += 256) {
            int n = i >> 4, kp = i & 15;
            unsigned gi = (unsigned)(col0 + n) * HD + k0 + kp * 2;
            *(unsigned*)&Bh[n * SSTR + kp * 2] = *(const unsigned*)&Wh[gi];
            *(unsigned*)&Bl[n * SSTR + kp * 2] = *(const unsigned*)&Wl[gi];
        }
        __syncthreads();

        #pragma unroll
        for (int ks = 0; ks < KC; ks += 16) {
            unsigned ah[2][4], al[2][4];
            #pragma unroll
            for (int mi = 0; mi < 2; mi++) {
                int r = wr0 + mi * 16 + lr;
                ah[mi][0] = *(const unsigned*)&Ah[r * SSTR + ks + lk];
                ah[mi][1] = *(const unsigned*)&Ah[(r + 8) * SSTR + ks + lk];
                ah[mi][2] = *(const unsigned*)&Ah[r * SSTR + ks + 8 + lk];
                ah[mi][3] = *(const unsigned*)&Ah[(r + 8) * SSTR + ks + 8 + lk];
                al[mi][0] = *(const unsigned*)&Al[r * SSTR + ks + lk];
                al[mi][1] = *(const unsigned*)&Al[(r + 8) * SSTR + ks + lk];
                al[mi][2] = *(const unsigned*)&Al[r * SSTR + ks + 8 + lk];
                al[mi][3] = *(const unsigned*)&Al[(r + 8) * SSTR + ks + 8 + lk];
            }
            unsigned bh[4][2], bl[4][2];
            #pragma unroll
            for (int nj = 0; nj < 4; nj++) {
                int n = wc0 + nj * 8 + lr;
                bh[nj][0] = *(const unsigned*)&Bh[n * SSTR + ks + lk];
                bh[nj][1] = *(const unsigned*)&Bh[n * SSTR + ks + 8 + lk];
                bl[nj][0] = *(const unsigned*)&Bl[n * SSTR + ks + lk];
                bl[nj][1] = *(const unsigned*)&Bl[n * SSTR + ks + 8 + lk];
            }
            #pragma unroll
            for (int mi = 0; mi < 2; mi++)
                #pragma unroll
                for (int nj = 0; nj < 4; nj++) {
                    float* d = acc[mi][nj];
                    mma_bf16(d[0], d[1], d[2], d[3],
                             ah[mi][0], ah[mi][1], ah[mi][2], ah[mi][3],
                             bh[nj][0], bh[nj][1]);
                    mma_bf16(d[0], d[1], d[2], d[3],
                             ah[mi][0], ah[mi][1], ah[mi][2], ah[mi][3],
                             bl[nj][0], bl[nj][1]);
                    mma_bf16(d[0], d[1], d[2], d[3],
                             al[mi][0], al[mi][1], al[mi][2], al[mi][3],
                             bh[nj][0], bh[nj][1]);
                }
        }
        __syncthreads();
    }

    #pragma unroll
    for (int mi = 0; mi < 2; mi++) {
        #pragma unroll
        for (int nj = 0; nj < 4; nj++) {
            int rloc = wr0 + mi * 16 + lr;
            int hloc = wc0 + nj * 8 + (lane & 3) * 2;
            #pragma unroll
            for (int half = 0; half < 2; half++) {
                int row = row0 + rloc + half * 8;
                float d0 = acc[mi][nj][half * 2];
                float d1 = acc[mi][nj][half * 2 + 1];
                int h = col0 + hloc;
                if (z == 2) {
                    g_Vm[row * HD + h]     = d0;
                    g_Vm[row * HD + h + 1] = d1;
                } else {
                    int s = row & (SEQ - 1);
                    float2 rt0 = g_rot[s * HD + h];
                    float2 rt1 = g_rot[s * HD + h + 1];
                    __nv_bfloat16* dh = (z == 0) ? g_QQh : g_KKh;
                    __nv_bfloat16* dl = (z == 0) ? g_QQl : g_KKl;
                    __nv_bfloat162 lo2;
                    __nv_bfloat162 hi2 = split_hi2(d0 * rt0.x, d1 * rt1.x, lo2);
                    *(__nv_bfloat162*)&dh[row * K2W + h] = hi2;
                    *(__nv_bfloat162*)&dl[row * K2W + h] = lo2;
                    hi2 = split_hi2(d0 * rt0.y, d1 * rt1.y, lo2);
                    *(__nv_bfloat162*)&dh[row * K2W + HD + h] = hi2;
                    *(__nv_bfloat162*)&dl[row * K2W + HD + h] = lo2;
                }
            }
        }
    }
}

// ---------------------------------------------------------------------------
// K2: att via mma.sync.  64x64 tile, 256 threads (8 warps, 32x16 each).
// grid (SEQ/64, NJ, BATCH)
// ---------------------------------------------------------------------------
__global__ __launch_bounds__(256) void att_kernel()
{
    __shared__ __align__(16) __nv_bfloat16 Qh[64 * SSTR];
    __shared__ __align__(16) __nv_bfloat16 Ql[64 * SSTR];
    __shared__ __align__(16) __nv_bfloat16 Kh[64 * SSTR];
    __shared__ __align__(16) __nv_bfloat16 Kl[64 * SSTR];

    const int b  = blockIdx.z;
    const int n0 = blockIdx.x * 64;
    const int m0 = n0 - 64 * (int)blockIdx.y;
    if (m0 < 0) return;

    const int tid  = threadIdx.x;
    const int wid  = tid >> 5;
    const int lane = tid & 31;
    const int wr0  = (wid & 1) * 32;      // warp rows (n)
    const int wc0  = (wid >> 1) * 16;     // warp cols (m)
    const int lr   = lane >> 2;
    const int lk   = (lane & 3) * 2;
    const long long qbase = (long long)(b * SEQ + n0) * K2W;
    const long long kbase = (long long)(b * SEQ + m0) * K2W;

    float acc[2][2][4] = {};

    for (int k0 = 0; k0 < K2W; k0 += KC) {
        for (int i = tid; i < 64 * (KC / 2); i += 256) {
            int r = i >> 4, kp = i & 15;
            long long gq = qbase + (long long)r * K2W + k0 + kp * 2;
            long long gk = kbase + (long long)r * K2W + k0 + kp * 2;
            *(unsigned*)&Qh[r * SSTR + kp * 2] = *(const unsigned*)&g_QQh[gq];
            *(unsigned*)&Ql[r * SSTR + kp * 2] = *(const unsigned*)&g_QQl[gq];
            *(unsigned*)&Kh[r * SSTR + kp * 2] = *(const unsigned*)&g_KKh[gk];
            *(unsigned*)&Kl[r * SSTR + kp * 2] = *(const unsigned*)&g_KKl[gk];
        }
        __syncthreads();

        #pragma unroll
        for (int ks = 0; ks < KC; ks += 16) {
            unsigned ah[2][4], al[2][4];
            #pragma unroll
            for (int mi = 0; mi < 2; mi++) {
                int r = wr0 + mi * 16 + lr;
                ah[mi][0] = *(const unsigned*)&Qh[r * SSTR + ks + lk];
                ah[mi][1] = *(const unsigned*)&Qh[(r + 8) * SSTR + ks + lk];
                ah[mi][2] = *(const unsigned*)&Qh[r * SSTR + ks + 8 + lk];
                ah[mi][3] = *(const unsigned*)&Qh[(r + 8) * SSTR + ks + 8 + lk];
                al[mi][0] = *(const unsigned*)&Ql[r * SSTR + ks + lk];
                al[mi][1] = *(const unsigned*)&Ql[(r + 8) * SSTR + ks + lk];
                al[mi][2] = *(const unsigned*)&Ql[r * SSTR + ks + 8 + lk];
                al[mi][3] = *(const unsigned*)&Ql[(r + 8) * SSTR + ks + 8 + lk];
            }
            unsigned bh[2][2], bl[2][2];
            #pragma unroll
            for (int nj = 0; nj < 2; nj++) {
                int n = wc0 + nj * 8 + lr;
                bh[nj][0] = *(const unsigned*)&Kh[n * SSTR + ks + lk];
                bh[nj][1] = *(const unsigned*)&Kh[n * SSTR + ks + 8 + lk];
                bl[nj][0] = *(const unsigned*)&Kl[n * SSTR + ks + lk];
                bl[nj][1] = *(const unsigned*)&Kl[n * SSTR + ks + 8 + lk];
            }
            #pragma unroll
            for (int mi = 0; mi < 2; mi++)
                #pragma unroll
                for (int nj = 0; nj < 2; nj++) {
                    float* d = acc[mi][nj];
                    mma_bf16(d[0], d[1], d[2], d[3],
                             ah[mi][0], ah[mi][1], ah[mi][2], ah[mi][3],
                             bh[nj][0], bh[nj][1]);
                    mma_bf16(d[0], d[1], d[2], d[3],
                             ah[mi][0], ah[mi][1], ah[mi][2], ah[mi][3],
                             bl[nj][0], bl[nj][1]);
                    mma_bf16(d[0], d[1], d[2], d[3],
                             al[mi][0], al[mi][1], al[mi][2], al[mi][3],
                             bh[nj][0], bh[nj][1]);
                }
        }
        __syncthreads();
    }

    // epilogue: decay + banded store
    #pragma unroll
    for (int mi = 0; mi < 2; mi++) {
        #pragma unroll
        for (int nj = 0; nj < 2; nj++) {
            #pragma unroll
            for (int half = 0; half < 2; half++) {
                int n = n0 + wr0 + mi * 16 + lr + half * 8;
                int m = m0 + wc0 + nj * 8 + (lane & 3) * 2;
                float d0 = acc[mi][nj][half * 2];
                float d1 = acc[mi][nj][half * 2 + 1];
                int dd0 = n - m, dd1 = n - m - 1;
                if (dd0 >= 0 && dd0 < WIN)
                    g_attR[(long long)(b * SEQ + n) * WIN + dd0] =
                        d0 * exp2f((float)dd0 * LOG2_GAMMA);
                if (dd1 >= 0 && dd1 < WIN)
                    g_attR[(long long)(b * SEQ + n) * WIN + dd1] =
                        d1 * exp2f((float)dd1 * LOG2_GAMMA);
            }
        }
    }
}

// ---------------------------------------------------------------------------
// K3: Re(out)[b,n,h] = sum_m attR[b,n,n-m] * V[b,m,h]   (R9 scalar config)
// ---------------------------------------------------------------------------
__global__ __launch_bounds__(256) void out_kernel(float* __restrict__ out,
                                                  long long out_elems)
{
    __shared__ __align__(16) float Ar[64][68];
    __shared__ __align__(16) float Vs[64][68];

    const int b  = blockIdx.z;
    const int n0 = blockIdx.x * 64;
    const int h0 = blockIdx.y * 64;
    const int tid = threadIdx.x;
    const int tx  = tid & 15, ty = tid >> 4;
    const int r0  = ty * 4,  c0 = tx * 4;

    float acc[4][4] = {};

    for (int jt = 0; jt < NJ; jt++) {
        int m0 = n0 - 64 * jt;
        if (m0 < 0) break;

        for (int i = tid; i < 64 * 64; i += 256) {
            int r = i >> 6, c = i & 63;
            Vs[r][c] = g_Vm[(b * SEQ + m0 + r) * HD + h0 + c];
        }
        for (int i = tid; i < 64 * 64; i += 256) {
            int nl = i >> 6, ml = i & 63;
            int d = 64 * jt + nl - ml;
            Ar[nl][ml] = (d >= 0 && d < WIN)
                       ? g_attR[(long long)(b * SEQ + n0 + nl) * WIN + d]
                       : 0.0f;
        }
        __syncthreads();

        #pragma unroll 8
        for (int m = 0; m < 64; m++) {
            float4 v = *(const float4*)&Vs[m][c0];
            const float vv[4] = {v.x, v.y, v.z, v.w};
            float ar[4];
            #pragma unroll
            for (int i = 0; i < 4; i++) ar[i] = Ar[r0 + i][m];
            #pragma unroll
            for (int i = 0; i < 4; i++)
                #pragma unroll
                for (int j = 0; j < 4; j++)
                    acc[i][j] += ar[i] * vv[j];
        }
        __syncthreads();
    }

    #pragma unroll
    for (int i = 0; i < 4; i++) {
        int n = n0 + r0 + i;
        #pragma unroll
        for (int j = 0; j < 4; j++) {
            int h = h0 + c0 + j;
            long long idx = ((long long)b * SEQ + n) * HD + h;
            if (idx < out_elems)
                out[idx] = acc[i][j];
        }
    }
}

// ---------------------------------------------------------------------------
// launch
// ---------------------------------------------------------------------------
extern "C" void kernel_launch(void* const* d_in, const int* in_sizes, int n_in,
                              void* d_out, int out_size)
{
    constexpr int XN = BATCH * SEQ * HD;
    constexpr int WN = HD * HD;
    constexpr int TN = HD;

    const float* X = nullptr;
    const float* theta = nullptr;
    const float* W[3] = {nullptr, nullptr, nullptr};
    int wn = 0;

    for (int i = 0; i < n_in; i++) {
        int s = in_sizes[i];
        if (s == XN)                X = (const float*)d_in[i];
        else if (s == TN)           theta = (const float*)d_in[i];
        else if (s == WN && wn < 3) W[wn++] = (const float*)d_in[i];
    }
    if (!X || !theta || wn < 3) return;

    float* out = (float*)d_out;

    rot_kernel<<<SEQ * HD / 256, 256>>>(theta);
    wconv_kernel<<<3 * HD * HD / 256, 256>>>(W[0], W[1], W[2]);
    proj_kernel<<<dim3(NROW / PM, HD / PN, 3), 256>>>(X);
    att_kernel<<<dim3(SEQ / 64, NJ, BATCH), 256>>>();
    out_kernel<<<dim3(SEQ / 64, HD / 64, BATCH), 256>>>(out, (long long)out_size);
}

// round 15
// speedup vs baseline: 1.6156x; 1.0286x over previous
#include <cuda_runtime.h>
#include <cuda_bf16.h>
#include <math.h>

// ---------------------------------------------------------------------------
// SimpleRetention (real-output build, all three GEMMs on mma.sync bf16 with
// hi/lo error-compensated split: hi*hi + hi*lo + lo*hi, fp32 accumulators).
// Re(out[b,n,h]) = sum_m gamma^(n-m)[n>=m] * Re(Q K^T)[b,n,m] * V[b,m,h]
// Decay window 128: gamma^128 ~ 1.4e-6 relative truncation (threshold 1e-3).
// ---------------------------------------------------------------------------

namespace {
constexpr int BATCH = 4;
constexpr int SEQ   = 2048;
constexpr int HD    = 256;
constexpr int K2W   = 2 * HD;             // 512
constexpr int WIN   = 128;
constexpr int NROW  = BATCH * SEQ;        // 8192
constexpr int NJ    = WIN / 64 + 1;       // 3
constexpr float LOG2_GAMMA = -0.15200309344504997f;

constexpr int PM = 128;                   // proj block M
constexpr int PN = 64;                    // proj block N
constexpr int KC = 32;                    // proj K chunk
constexpr int SSTR = KC + 8;              // proj smem stride = 40

constexpr int KC2 = 64;                   // att/out K chunk
constexpr int SST2 = KC2 + 8;             // att/out smem stride = 72
}

// scratch
__device__ float2        g_rot  [SEQ * HD];
__device__ __nv_bfloat16 g_QQh  [NROW * K2W];
__device__ __nv_bfloat16 g_QQl  [NROW * K2W];
__device__ __nv_bfloat16 g_KKh  [NROW * K2W];
__device__ __nv_bfloat16 g_KKl  [NROW * K2W];
__device__ float         g_Vm   [NROW * HD];
__device__ __nv_bfloat16 g_Vth  [HD * NROW];   // V^T split hi  [h][m]
__device__ __nv_bfloat16 g_Vtl  [HD * NROW];
__device__ __nv_bfloat16 g_bandh[NROW * WIN];  // decayed band, split hi
__device__ __nv_bfloat16 g_bandl[NROW * WIN];
__device__ __nv_bfloat16 g_Wh   [3 * HD * HD];
__device__ __nv_bfloat16 g_Wl   [3 * HD * HD];

__device__ __forceinline__ __nv_bfloat162 split_hi2(float a, float b,
                                                    __nv_bfloat162& lo)
{
    __nv_bfloat16 h0 = __float2bfloat16(a);
    __nv_bfloat16 h1 = __float2bfloat16(b);
    lo = __nv_bfloat162(__float2bfloat16(a - __bfloat162float(h0)),
                        __float2bfloat16(b - __bfloat162float(h1)));
    return __nv_bfloat162(h0, h1);
}

__device__ __forceinline__ void mma_bf16(
    float& d0, float& d1, float& d2, float& d3,
    unsigned a0, unsigned a1, unsigned a2, unsigned a3,
    unsigned b0, unsigned b1)
{
    asm volatile(
        "mma.sync.aligned.m16n8k16.row.col.f32.bf16.bf16.f32 "
        "{%0,%1,%2,%3}, {%4,%5,%6,%7}, {%8,%9}, {%0,%1,%2,%3};"
        : "+f"(d0), "+f"(d1), "+f"(d2), "+f"(d3)
        : "r"(a0), "r"(a1), "r"(a2), "r"(a3), "r"(b0), "r"(b1));
}

// ---------------------------------------------------------------------------
// K0: rotation table
// ---------------------------------------------------------------------------
__global__ __launch_bounds__(256) void rot_kernel(const float* __restrict__ theta)
{
    int idx = blockIdx.x * 256 + threadIdx.x;
    int s = idx >> 8;
    int h = idx & (HD - 1);
    float ph = (float)(s + 1) * theta[h];
    float sn, cs;
    sincosf(ph, &sn, &cs);
    g_rot[idx] = make_float2(cs, sn);
}

// ---------------------------------------------------------------------------
// K0b: transpose + bf16-split weights:  g_W{h,l}[w][n][k] = W[w][k][n]
// ---------------------------------------------------------------------------
__global__ __launch_bounds__(256) void wconv_kernel(
    const float* __restrict__ W0, const float* __restrict__ W1,
    const float* __restrict__ W2)
{
    int o = blockIdx.x * 256 + threadIdx.x;
    int w = o >> 16;
    int n = (o >> 8) & 255;
    int k = o & 255;
    const float* W = (w == 0) ? W0 : (w == 1) ? W1 : W2;
    float x = W[k * HD + n];
    __nv_bfloat16 hi = __float2bfloat16(x);
    g_Wh[o] = hi;
    g_Wl[o] = __float2bfloat16(x - __bfloat162float(hi));
}

// ---------------------------------------------------------------------------
// K0c: V^T split:  g_Vt{h,l}[h][m] = split(g_Vm[m][h]).  Tiled transpose.
// grid (NROW/32, HD/32), block (32, 8)
// ---------------------------------------------------------------------------
__global__ __launch_bounds__(256) void vtconv_kernel()
{
    __shared__ float t[32][33];
    const int mx = blockIdx.x * 32;
    const int hy = blockIdx.y * 32;
    const int tx = threadIdx.x, ty = threadIdx.y;

    #pragma unroll
    for (int j = 0; j < 4; j++)
        t[ty + j * 8][tx] = g_Vm[(mx + ty + j * 8) * HD + hy + tx];
    __syncthreads();

    #pragma unroll
    for (int j = 0; j < 4; j++) {
        int h = hy + ty + j * 8;
        float v = t[tx][ty + j * 8];
        __nv_bfloat16 hi = __float2bfloat16(v);
        g_Vth[(long long)h * NROW + mx + tx] = hi;
        g_Vtl[(long long)h * NROW + mx + tx] =
            __float2bfloat16(v - __bfloat162float(hi));
    }
}

// ---------------------------------------------------------------------------
// K1: proj via mma.sync.  grid (NROW/128, HD/64, 3), 256 threads.
// ---------------------------------------------------------------------------
__global__ __launch_bounds__(256) void proj_kernel(const float* __restrict__ X)
{
    __shared__ __align__(16) __nv_bfloat16 Ah[PM * SSTR];
    __shared__ __align__(16) __nv_bfloat16 Al[PM * SSTR];
    __shared__ __align__(16) __nv_bfloat16 Bh[PN * SSTR];
    __shared__ __align__(16) __nv_bfloat16 Bl[PN * SSTR];

    const int tid  = threadIdx.x;
    const int wid  = tid >> 5;
    const int lane = tid & 31;
    const int row0 = blockIdx.x * PM;
    const int col0 = blockIdx.y * PN;
    const int z    = blockIdx.z;

    const int wr0 = (wid & 3) * 32;
    const int wc0 = (wid >> 2) * 32;
    const int lr  = lane >> 2;
    const int lk  = (lane & 3) * 2;

    const __nv_bfloat16* Wh = g_Wh + z * HD * HD;
    const __nv_bfloat16* Wl = g_Wl + z * HD * HD;

    float acc[2][4][4] = {};

    for (int k0 = 0; k0 < HD; k0 += KC) {
        for (int i = tid; i < PM * (KC / 2); i += 256) {
            int r = i >> 4, kp = i & 15;
            float2 x2 = *(const float2*)&X[(row0 + r) * HD + k0 + kp * 2];
            __nv_bfloat162 lo2;
            __nv_bfloat162 hi2 = split_hi2(x2.x, x2.y, lo2);
            *(__nv_bfloat162*)&Ah[r * SSTR + kp * 2] = hi2;
            *(__nv_bfloat162*)&Al[r * SSTR + kp * 2] = lo2;
        }
        for (int i = tid; i < PN * (KC / 2); i += 256) {
            int n = i >> 4, kp = i & 15;
            unsigned gi = (unsigned)(col0 + n) * HD + k0 + kp * 2;
            *(unsigned*)&Bh[n * SSTR + kp * 2] = *(const unsigned*)&Wh[gi];
            *(unsigned*)&Bl[n * SSTR + kp * 2] = *(const unsigned*)&Wl[gi];
        }
        __syncthreads();

        #pragma unroll
        for (int ks = 0; ks < KC; ks += 16) {
            unsigned ah[2][4], al[2][4];
            #pragma unroll
            for (int mi = 0; mi < 2; mi++) {
                int r = wr0 + mi * 16 + lr;
                ah[mi][0] = *(const unsigned*)&Ah[r * SSTR + ks + lk];
                ah[mi][1] = *(const unsigned*)&Ah[(r + 8) * SSTR + ks + lk];
                ah[mi][2] = *(const unsigned*)&Ah[r * SSTR + ks + 8 + lk];
                ah[mi][3] = *(const unsigned*)&Ah[(r + 8) * SSTR + ks + 8 + lk];
                al[mi][0] = *(const unsigned*)&Al[r * SSTR + ks + lk];
                al[mi][1] = *(const unsigned*)&Al[(r + 8) * SSTR + ks + lk];
                al[mi][2] = *(const unsigned*)&Al[r * SSTR + ks + 8 + lk];
                al[mi][3] = *(const unsigned*)&Al[(r + 8) * SSTR + ks + 8 + lk];
            }
            unsigned bh[4][2], bl[4][2];
            #pragma unroll
            for (int nj = 0; nj < 4; nj++) {
                int n = wc0 + nj * 8 + lr;
                bh[nj][0] = *(const unsigned*)&Bh[n * SSTR + ks + lk];
                bh[nj][1] = *(const unsigned*)&Bh[n * SSTR + ks + 8 + lk];
                bl[nj][0] = *(const unsigned*)&Bl[n * SSTR + ks + lk];
                bl[nj][1] = *(const unsigned*)&Bl[n * SSTR + ks + 8 + lk];
            }
            #pragma unroll
            for (int mi = 0; mi < 2; mi++)
                #pragma unroll
                for (int nj = 0; nj < 4; nj++) {
                    float* d = acc[mi][nj];
                    mma_bf16(d[0], d[1], d[2], d[3],
                             ah[mi][0], ah[mi][1], ah[mi][2], ah[mi][3],
                             bh[nj][0], bh[nj][1]);
                    mma_bf16(d[0], d[1], d[2], d[3],
                             ah[mi][0], ah[mi][1], ah[mi][2], ah[mi][3],
                             bl[nj][0], bl[nj][1]);
                    mma_bf16(d[0], d[1], d[2], d[3],
                             al[mi][0], al[mi][1], al[mi][2], al[mi][3],
                             bh[nj][0], bh[nj][1]);
                }
        }
        __syncthreads();
    }

    #pragma unroll
    for (int mi = 0; mi < 2; mi++) {
        #pragma unroll
        for (int nj = 0; nj < 4; nj++) {
            int rloc = wr0 + mi * 16 + lr;
            int hloc = wc0 + nj * 8 + (lane & 3) * 2;
            #pragma unroll
            for (int half = 0; half < 2; half++) {
                int row = row0 + rloc + half * 8;
                float d0 = acc[mi][nj][half * 2];
                float d1 = acc[mi][nj][half * 2 + 1];
                int h = col0 + hloc;
                if (z == 2) {
                    g_Vm[row * HD + h]     = d0;
                    g_Vm[row * HD + h + 1] = d1;
                } else {
                    int s = row & (SEQ - 1);
                    float2 rt0 = g_rot[s * HD + h];
                    float2 rt1 = g_rot[s * HD + h + 1];
                    __nv_bfloat16* dh = (z == 0) ? g_QQh : g_KKh;
                    __nv_bfloat16* dl = (z == 0) ? g_QQl : g_KKl;
                    __nv_bfloat162 lo2;
                    __nv_bfloat162 hi2 = split_hi2(d0 * rt0.x, d1 * rt1.x, lo2);
                    *(__nv_bfloat162*)&dh[row * K2W + h] = hi2;
                    *(__nv_bfloat162*)&dl[row * K2W + h] = lo2;
                    hi2 = split_hi2(d0 * rt0.y, d1 * rt1.y, lo2);
                    *(__nv_bfloat162*)&dh[row * K2W + HD + h] = hi2;
                    *(__nv_bfloat162*)&dl[row * K2W + HD + h] = lo2;
                }
            }
        }
    }
}

// ---------------------------------------------------------------------------
// K2: att via mma.sync, K chunks of 64.  grid (SEQ/64, NJ, BATCH), 256 thr.
// Band stored as split bf16 with decay applied.
// ---------------------------------------------------------------------------
__global__ __launch_bounds__(256) void att_kernel()
{
    __shared__ __align__(16) __nv_bfloat16 Qh[64 * SST2];
    __shared__ __align__(16) __nv_bfloat16 Ql[64 * SST2];
    __shared__ __align__(16) __nv_bfloat16 Kh[64 * SST2];
    __shared__ __align__(16) __nv_bfloat16 Kl[64 * SST2];

    const int b  = blockIdx.z;
    const int n0 = blockIdx.x * 64;
    const int m0 = n0 - 64 * (int)blockIdx.y;
    if (m0 < 0) return;

    const int tid  = threadIdx.x;
    const int wid  = tid >> 5;
    const int lane = tid & 31;
    const int wr0  = (wid & 1) * 32;
    const int wc0  = (wid >> 1) * 16;
    const int lr   = lane >> 2;
    const int lk   = (lane & 3) * 2;
    const long long qbase = (long long)(b * SEQ + n0) * K2W;
    const long long kbase = (long long)(b * SEQ + m0) * K2W;

    float acc[2][2][4] = {};

    for (int k0 = 0; k0 < K2W; k0 += KC2) {
        for (int i = tid; i < 64 * (KC2 / 2); i += 256) {
            int r = i >> 5, kp = i & 31;
            long long gq = qbase + (long long)r * K2W + k0 + kp * 2;
            long long gk = kbase + (long long)r * K2W + k0 + kp * 2;
            *(unsigned*)&Qh[r * SST2 + kp * 2] = *(const unsigned*)&g_QQh[gq];
            *(unsigned*)&Ql[r * SST2 + kp * 2] = *(const unsigned*)&g_QQl[gq];
            *(unsigned*)&Kh[r * SST2 + kp * 2] = *(const unsigned*)&g_KKh[gk];
            *(unsigned*)&Kl[r * SST2 + kp * 2] = *(const unsigned*)&g_KKl[gk];
        }
        __syncthreads();

        #pragma unroll
        for (int ks = 0; ks < KC2; ks += 16) {
            unsigned ah[2][4], al[2][4];
            #pragma unroll
            for (int mi = 0; mi < 2; mi++) {
                int r = wr0 + mi * 16 + lr;
                ah[mi][0] = *(const unsigned*)&Qh[r * SST2 + ks + lk];
                ah[mi][1] = *(const unsigned*)&Qh[(r + 8) * SST2 + ks + lk];
                ah[mi][2] = *(const unsigned*)&Qh[r * SST2 + ks + 8 + lk];
                ah[mi][3] = *(const unsigned*)&Qh[(r + 8) * SST2 + ks + 8 + lk];
                al[mi][0] = *(const unsigned*)&Ql[r * SST2 + ks + lk];
                al[mi][1] = *(const unsigned*)&Ql[(r + 8) * SST2 + ks + lk];
                al[mi][2] = *(const unsigned*)&Ql[r * SST2 + ks + 8 + lk];
                al[mi][3] = *(const unsigned*)&Ql[(r + 8) * SST2 + ks + 8 + lk];
            }
            unsigned bh[2][2], bl[2][2];
            #pragma unroll
            for (int nj = 0; nj < 2; nj++) {
                int n = wc0 + nj * 8 + lr;
                bh[nj][0] = *(const unsigned*)&Kh[n * SST2 + ks + lk];
                bh[nj][1] = *(const unsigned*)&Kh[n * SST2 + ks + 8 + lk];
                bl[nj][0] = *(const unsigned*)&Kl[n * SST2 + ks + lk];
                bl[nj][1] = *(const unsigned*)&Kl[n * SST2 + ks + 8 + lk];
            }
            #pragma unroll
            for (int mi = 0; mi < 2; mi++)
                #pragma unroll
                for (int nj = 0; nj < 2; nj++) {
                    float* d = acc[mi][nj];
                    mma_bf16(d[0], d[1], d[2], d[3],
                             ah[mi][0], ah[mi][1], ah[mi][2], ah[mi][3],
                             bh[nj][0], bh[nj][1]);
                    mma_bf16(d[0], d[1], d[2], d[3],
                             ah[mi][0], ah[mi][1], ah[mi][2], ah[mi][3],
                             bl[nj][0], bl[nj][1]);
                    mma_bf16(d[0], d[1], d[2], d[3],
                             al[mi][0], al[mi][1], al[mi][2], al[mi][3],
                             bh[nj][0], bh[nj][1]);
                }
        }
        __syncthreads();
    }

    #pragma unroll
    for (int mi = 0; mi < 2; mi++) {
        #pragma unroll
        for (int nj = 0; nj < 2; nj++) {
            #pragma unroll
            for (int half = 0; half < 2; half++) {
                int n = n0 + wr0 + mi * 16 + lr + half * 8;
                int m = m0 + wc0 + nj * 8 + (lane & 3) * 2;
                float d0 = acc[mi][nj][half * 2];
                float d1 = acc[mi][nj][half * 2 + 1];
                int dd0 = n - m, dd1 = n - m - 1;
                if (dd0 >= 0 && dd0 < WIN) {
                    float v = d0 * exp2f((float)dd0 * LOG2_GAMMA);
                    __nv_bfloat16 hi = __float2bfloat16(v);
                    long long ix = (long long)(b * SEQ + n) * WIN + dd0;
                    g_bandh[ix] = hi;
                    g_bandl[ix] = __float2bfloat16(v - __bfloat162float(hi));
                }
                if (dd1 >= 0 && dd1 < WIN) {
                    float v = d1 * exp2f((float)dd1 * LOG2_GAMMA);
                    __nv_bfloat16 hi = __float2bfloat16(v);
                    long long ix = (long long)(b * SEQ + n) * WIN + dd1;
                    g_bandh[ix] = hi;
                    g_bandl[ix] = __float2bfloat16(v - __bfloat162float(hi));
                }
            }
        }
    }
}

// ---------------------------------------------------------------------------
// K3: out via mma.sync.  D[n][h] = sum_m band[n][m] * Vt[h][m].
// grid (SEQ/64, HD/64, BATCH), 256 threads, 3 m-tiles of K=64 each.
// ---------------------------------------------------------------------------
__global__ __launch_bounds__(256) void out_kernel(float* __restrict__ out,
                                                  long long out_elems)
{
    __shared__ __align__(16) __nv_bfloat16 Ah[64 * SST2];
    __shared__ __align__(16) __nv_bfloat16 Al[64 * SST2];
    __shared__ __align__(16) __nv_bfloat16 Vh[64 * SST2];
    __shared__ __align__(16) __nv_bfloat16 Vl[64 * SST2];

    const int b  = blockIdx.z;
    const int n0 = blockIdx.x * 64;
    const int h0 = blockIdx.y * 64;
    const int tid  = threadIdx.x;
    const int wid  = tid >> 5;
    const int lane = tid & 31;
    const int wr0  = (wid & 1) * 32;      // n rows
    const int wc0  = (wid >> 1) * 16;     // h cols
    const int lr   = lane >> 2;
    const int lk   = (lane & 3) * 2;

    float acc[2][2][4] = {};

    for (int jt = 0; jt < NJ; jt++) {
        int m0 = n0 - 64 * jt;
        if (m0 < 0) break;

        // A tile: band[n][m] split, from banded storage (d = n-m)
        for (int i = tid; i < 64 * 64; i += 256) {
            int nl = i >> 6, ml = i & 63;
            int d = 64 * jt + nl - ml;
            __nv_bfloat16 hi(0.f), lo(0.f);
            if (d >= 0 && d < WIN) {
                long long ix = (long long)(b * SEQ + n0 + nl) * WIN + d;
                hi = g_bandh[ix];
                lo = g_bandl[ix];
            }
            Ah[nl * SST2 + ml] = hi;
            Al[nl * SST2 + ml] = lo;
        }
        // B tile: Vt[h][m] split (pre-transposed), coalesced over m
        for (int i = tid; i < 64 * (KC2 / 2); i += 256) {
            int r = i >> 5, kp = i & 31;     // r = h local, kp*2 = m local
            long long gi = (long long)(h0 + r) * NROW + b * SEQ + m0 + kp * 2;
            *(unsigned*)&Vh[r * SST2 + kp * 2] = *(const unsigned*)&g_Vth[gi];
            *(unsigned*)&Vl[r * SST2 + kp * 2] = *(const unsigned*)&g_Vtl[gi];
        }
        __syncthreads();

        #pragma unroll
        for (int ks = 0; ks < KC2; ks += 16) {
            unsigned ah[2][4], al[2][4];
            #pragma unroll
            for (int mi = 0; mi < 2; mi++) {
                int r = wr0 + mi * 16 + lr;
                ah[mi][0] = *(const unsigned*)&Ah[r * SST2 + ks + lk];
                ah[mi][1] = *(const unsigned*)&Ah[(r + 8) * SST2 + ks + lk];
                ah[mi][2] = *(const unsigned*)&Ah[r * SST2 + ks + 8 + lk];
                ah[mi][3] = *(const unsigned*)&Ah[(r + 8) * SST2 + ks + 8 + lk];
                al[mi][0] = *(const unsigned*)&Al[r * SST2 + ks + lk];
                al[mi][1] = *(const unsigned*)&Al[(r + 8) * SST2 + ks + lk];
                al[mi][2] = *(const unsigned*)&Al[r * SST2 + ks + 8 + lk];
                al[mi][3] = *(const unsigned*)&Al[(r + 8) * SST2 + ks + 8 + lk];
            }
            unsigned bh[2][2], bl[2][2];
            #pragma unroll
            for (int nj = 0; nj < 2; nj++) {
                int n = wc0 + nj * 8 + lr;
                bh[nj][0] = *(const unsigned*)&Vh[n * SST2 + ks + lk];
                bh[nj][1] = *(const unsigned*)&Vh[n * SST2 + ks + 8 + lk];
                bl[nj][0] = *(const unsigned*)&Vl[n * SST2 + ks + lk];
                bl[nj][1] = *(const unsigned*)&Vl[n * SST2 + ks + 8 + lk];
            }
            #pragma unroll
            for (int mi = 0; mi < 2; mi++)
                #pragma unroll
                for (int nj = 0; nj < 2; nj++) {
                    float* d = acc[mi][nj];
                    mma_bf16(d[0], d[1], d[2], d[3],
                             ah[mi][0], ah[mi][1], ah[mi][2], ah[mi][3],
                             bh[nj][0], bh[nj][1]);
                    mma_bf16(d[0], d[1], d[2], d[3],
                             ah[mi][0], ah[mi][1], ah[mi][2], ah[mi][3],
                             bl[nj][0], bl[nj][1]);
                    mma_bf16(d[0], d[1], d[2], d[3],
                             al[mi][0], al[mi][1], al[mi][2], al[mi][3],
                             bh[nj][0], bh[nj][1]);
                }
        }
        __syncthreads();
    }

    #pragma unroll
    for (int mi = 0; mi < 2; mi++) {
        #pragma unroll
        for (int nj = 0; nj < 2; nj++) {
            #pragma unroll
            for (int half = 0; half < 2; half++) {
                int n = n0 + wr0 + mi * 16 + lr + half * 8;
                int h = h0 + wc0 + nj * 8 + (lane & 3) * 2;
                long long idx = ((long long)b * SEQ + n) * HD + h;
                if (idx + 1 < out_elems) {
                    out[idx]     = acc[mi][nj][half * 2];
                    out[idx + 1] = acc[mi][nj][half * 2 + 1];
                }
            }
        }
    }
}

// ---------------------------------------------------------------------------
// launch
// ---------------------------------------------------------------------------
extern "C" void kernel_launch(void* const* d_in, const int* in_sizes, int n_in,
                              void* d_out, int out_size)
{
    constexpr int XN = BATCH * SEQ * HD;
    constexpr int WN = HD * HD;
    constexpr int TN = HD;

    const float* X = nullptr;
    const float* theta = nullptr;
    const float* W[3] = {nullptr, nullptr, nullptr};
    int wn = 0;

    for (int i = 0; i < n_in; i++) {
        int s = in_sizes[i];
        if (s == XN)                X = (const float*)d_in[i];
        else if (s == TN)           theta = (const float*)d_in[i];
        else if (s == WN && wn < 3) W[wn++] = (const float*)d_in[i];
    }
    if (!X || !theta || wn < 3) return;

    float* out = (float*)d_out;

    rot_kernel<<<SEQ * HD / 256, 256>>>(theta);
    wconv_kernel<<<3 * HD * HD / 256, 256>>>(W[0], W[1], W[2]);
    proj_kernel<<<dim3(NROW / PM, HD / PN, 3), 256>>>(X);
    vtconv_kernel<<<dim3(NROW / 32, HD / 32), dim3(32, 8)>>>();
    att_kernel<<<dim3(SEQ / 64, NJ, BATCH), 256>>>();
    out_kernel<<<dim3(SEQ / 64, HD / 64, BATCH), 256>>>(out, (long long)out_size);
}